// round 10
// baseline (speedup 1.0000x reference)
#include <cuda_runtime.h>
#include <cstdint>

#define NB    32
#define CIN   256
#define HH    56
#define WW    56
#define KOUT  256
#define NPIX  (HH*WW)        // 3136
#define KDIM  (CIN*9)        // 2304
#define NCHUNK 72            // 2304 / 32 k-chunks

#define MTILE 128            // out channels per CTA
#define NTILE 112            // pixels per CTA (2 rows x 56)

// stage layout (bytes), 128B k-rows of tf32: A 128x128B, B 112x128B
#define A_OFF  0
#define B_OFF  16384
#define STAGE  30720
#define SM_DYN (3*STAGE + 128)   // 92288/CTA -> 2 CTAs/SM

// ---------------- device scratch -------------------------------------------
__device__ __align__(16) float g_wt[KOUT * KDIM];               // tf32-rounded
__device__ __align__(16) float g_xt[(size_t)NB * NPIX * CIN];   // NHWC tf32

// ---------------- PTX helpers ----------------------------------------------
__device__ __forceinline__ uint32_t smem_u32(const void* p) {
    uint32_t a;
    asm("{ .reg .u64 t; cvta.to.shared.u64 t, %1; cvt.u32.u64 %0, t; }"
        : "=r"(a) : "l"(p));
    return a;
}
__device__ __forceinline__ float to_tf32(float v) {
    uint32_t r;
    asm("cvt.rna.tf32.f32 %0, %1;" : "=r"(r) : "f"(v));
    return __uint_as_float(r);
}

#define CP16(dst, src, sz) \
    asm volatile("cp.async.cg.shared.global [%0], [%1], 16, %2;" \
                 :: "r"(dst), "l"(src), "r"(sz) : "memory")
#define CP_COMMIT() asm volatile("cp.async.commit_group;" ::: "memory")
#define CP_WAIT1()  asm volatile("cp.async.wait_group 1;" ::: "memory")
#define CP_WAIT0()  asm volatile("cp.async.wait_group 0;" ::: "memory")

#define LDSM4(r, a) \
    asm volatile("ldmatrix.sync.aligned.m8n8.x4.shared.b16 {%0,%1,%2,%3}, [%4];" \
                 : "=r"((r)[0]),"=r"((r)[1]),"=r"((r)[2]),"=r"((r)[3]) : "r"(a))
#define LDSM2(r, a) \
    asm volatile("ldmatrix.sync.aligned.m8n8.x2.shared.b16 {%0,%1}, [%2];" \
                 : "=r"((r)[0]),"=r"((r)[1]) : "r"(a))

#define MMAT(d, a, b) \
    asm volatile("mma.sync.aligned.m16n8k8.row.col.f32.tf32.tf32.f32 " \
                 "{%0,%1,%2,%3}, {%4,%5,%6,%7}, {%8,%9}, {%0,%1,%2,%3};" \
                 : "+f"((d)[0]),"+f"((d)[1]),"+f"((d)[2]),"+f"((d)[3]) \
                 : "r"((a)[0]),"r"((a)[1]),"r"((a)[2]),"r"((a)[3]), \
                   "r"((b)[0]),"r"((b)[1]))

// ---------------- fused prepass ---------------------------------------------
__global__ void prepass_all(const float* __restrict__ x,
                            const float* __restrict__ w) {
    __shared__ float t[32][33];
    const int tx = threadIdx.x, ty = threadIdx.y;   // 32 x 8

    if (blockIdx.z < NB) {
        const int n  = blockIdx.z;
        const int p0 = blockIdx.x * 32;
        const int c0 = blockIdx.y * 32;

        const float* xb = x + ((size_t)n * CIN + c0) * NPIX + p0;
        #pragma unroll
        for (int yy = ty; yy < 32; yy += 8)
            t[yy][tx] = xb[(size_t)yy * NPIX + tx];
        __syncthreads();

        size_t ob = ((size_t)n * NPIX + p0) * CIN + c0;
        #pragma unroll
        for (int yy = ty; yy < 32; yy += 8)
            g_xt[ob + (size_t)yy * CIN + tx] = to_tf32(t[tx][yy]);
    } else {
        const int b = blockIdx.y * gridDim.x + blockIdx.x;   // 0..783
        const int tl = ty * 32 + tx;
        for (int i = b * 256 + tl; i < KOUT * KDIM; i += 784 * 256) {
            int k = i / KDIM, r = i % KDIM;
            int c = r / 9, tap = r % 9;
            g_wt[k * KDIM + tap * CIN + c] = to_tf32(w[i]);
        }
    }
}

// ---------------- main kernel ------------------------------------------------
__global__ __launch_bounds__(256, 2)
void conv_mma_kernel(const float* __restrict__ bias, float* __restrict__ out)
{
    extern __shared__ __align__(16) char dsm_raw[];

    const int tid = threadIdx.x;
    const int wid = tid >> 5;
    const int L   = tid & 31;
    const int wm  = wid & 3;             // M group (out-ch quarter)
    const int wn  = wid >> 2;            // N group (pixel row)
    // per-warp k-step rotation: anti-phase the two warps on each SMSP
    const int kso = (wid & 3) ^ ((wid >> 2) << 1);

    const int r0 = blockIdx.x * 2;       // output row base
    const int k0 = blockIdx.y * MTILE;   // out-channel base
    const int n  = blockIdx.z;           // image

    uint32_t raw = smem_u32(dsm_raw);
    uint32_t sm  = (raw + 127u) & ~127u;
    uint32_t bufs[3] = { sm, sm + STAGE, sm + 2 * STAGE };

    // ---- per-lane ldmatrix constants (tf32 k8 fragments via b16 ldmatrix) ----
    const int arowL = ((L >> 3) & 1) * 8 + (L & 7);
    const int akg   = L >> 4;            // A k 16B-group parity
    const int bprowL = wn * 56 + ((L >> 4) & 1) * 8 + (L & 7);
    const int bpkg   = (L >> 3) & 1;
    const int bsrowL = wn * 56 + 48 + (L & 7);
    const int bskg   = (L >> 3) & 1;

    // ---- persistent staging state ----
    uint32_t giB[4], giA[4], szmask;

    auto setup_tap = [&](int tap) {
        const int kh = tap / 3 - 1, kw = tap % 3 - 1;
        uint32_t m = 0;
        #pragma unroll
        for (int s = 0; s < 4; ++s) {
            const int i = tid + s * 256;
            const int p = i >> 3, v = i & 7;
            const int r = r0 + p / 56 + kh;
            const int w = p % 56 + kw;
            const bool in = ((unsigned)r < HH) & ((unsigned)w < WW);
            giB[s] = in ? (uint32_t)((n * NPIX + r * WW + w) * CIN + v * 4) : 0u;
            if (in) m |= (1u << s);
            giA[s] = (uint32_t)((k0 + p) * KDIM + tap * CIN + v * 4);
        }
        szmask = m;
    };
    auto slot_off = [&](int s) -> uint32_t {
        const int i = tid + s * 256;
        const int p = i >> 3, v = i & 7;
        uint32_t bo = (uint32_t)(p << 7) + (v << 4);
        return bo ^ ((bo >> 3) & 0x70);
    };
    auto emitB2 = [&](uint32_t sb, int s0) {
        #pragma unroll
        for (int ss = s0; ss < s0 + 2; ++ss) {
            const uint32_t sz = ((szmask >> ss) & 1u) * 16u;
            if (ss < 3 || tid < 128)
                CP16(sb + B_OFF + slot_off(ss), g_xt + giB[ss], sz);
        }
    };
    auto emitA2 = [&](uint32_t sb, int s0) {
        #pragma unroll
        for (int ss = s0; ss < s0 + 2; ++ss)
            CP16(sb + A_OFF + slot_off(ss), g_wt + giA[ss], 16u);
    };
    auto advance = [&]() {
        #pragma unroll
        for (int s = 0; s < 4; ++s) { giB[s] += 32; giA[s] += 32; }
    };

    float acc[2][7][4];
    #pragma unroll
    for (int mi = 0; mi < 2; ++mi)
        #pragma unroll
        for (int ni = 0; ni < 7; ++ni)
            #pragma unroll
            for (int q = 0; q < 4; ++q)
                acc[mi][ni][q] = 0.0f;

    // ---- prologue: stage chunks 0 and 1 ----
    setup_tap(0);
    emitB2(bufs[0], 0); emitB2(bufs[0], 2); emitA2(bufs[0], 0); emitA2(bufs[0], 2);
    CP_COMMIT(); advance();
    emitB2(bufs[1], 0); emitB2(bufs[1], 2); emitA2(bufs[1], 0); emitA2(bufs[1], 2);
    CP_COMMIT(); advance();

    // ---- main loop ----
    int rd = 0, wr = 2;
    #pragma unroll 1
    for (int ch = 0; ch < NCHUNK; ++ch) {
        const int ce = ch + 2;
        const bool de = (ce < NCHUNK);
        if (de && (ce & 7) == 0) setup_tap(ce >> 3);

        if (ch + 1 < NCHUNK) CP_WAIT1();
        else                 CP_WAIT0();
        __syncthreads();

        const uint32_t sb = bufs[rd], wb = bufs[wr];
        const uint32_t sA = sb + A_OFF, sB = sb + B_OFF;

        #pragma unroll
        for (int kk = 0; kk < 4; ++kk) {        // four k8 steps, warp-rotated
            const int ks = (kk + kso) & 3;
            uint32_t bt[7][2];
            #pragma unroll
            for (int pi = 0; pi < 3; ++pi) {    // ni pairs 0-1, 2-3, 4-5
                const int row = bprowL + pi * 16;
                const int c16 = (ks * 2 + bpkg) ^ (row & 7);
                LDSM4(&bt[pi * 2][0], sB + (uint32_t)(row << 7) + (c16 << 4));
            }
            {                                   // ni = 6
                const int c16 = (ks * 2 + bskg) ^ (bsrowL & 7);
                LDSM2(bt[6], sB + (uint32_t)(bsrowL << 7) + (c16 << 4));
            }
            uint32_t at[2][4];
            #pragma unroll
            for (int mi = 0; mi < 2; ++mi) {
                const int row = wm * 32 + mi * 16 + arowL;
                const int c16 = (ks * 2 + akg) ^ (row & 7);
                LDSM4(at[mi], sA + (uint32_t)(row << 7) + (c16 << 4));
            }

            // interleaved staging for chunk ch+2 (keyed to kk: uniform order)
            if (de) {
                if      (kk == 0) emitB2(wb, 0);
                else if (kk == 1) emitB2(wb, 2);
                else if (kk == 2) emitA2(wb, 0);
                else { emitA2(wb, 2); CP_COMMIT(); advance(); }
            }

            #pragma unroll
            for (int mi = 0; mi < 2; ++mi)
                #pragma unroll
                for (int ni = 0; ni < 7; ++ni)
                    MMAT(acc[mi][ni], at[mi], bt[ni]);
        }

        rd = (rd == 2) ? 0 : rd + 1;
        wr = (wr == 2) ? 0 : wr + 1;
    }

    // ---- epilogue: bias + store ----
    const int gID = L >> 2;
    const int tig = L & 3;
    const int r   = r0 + wn;
    #pragma unroll
    for (int mi = 0; mi < 2; ++mi) {
        const int kbase = k0 + wm * 32 + mi * 16 + gID;
        const float b0 = bias[kbase];
        const float b1 = bias[kbase + 8];
        float* o0 = out + (((size_t)n * KOUT + kbase)     * HH + r) * WW;
        float* o1 = out + (((size_t)n * KOUT + kbase + 8) * HH + r) * WW;
        #pragma unroll
        for (int ni = 0; ni < 7; ++ni) {
            const int c = ni * 8 + tig * 2;
            float2 v0 = make_float2(acc[mi][ni][0] + b0, acc[mi][ni][1] + b0);
            float2 v1 = make_float2(acc[mi][ni][2] + b1, acc[mi][ni][3] + b1);
            *reinterpret_cast<float2*>(o0 + c) = v0;
            *reinterpret_cast<float2*>(o1 + c) = v1;
        }
    }
}

// ---------------- launch -----------------------------------------------------
extern "C" void kernel_launch(void* const* d_in, const int* in_sizes, int n_in,
                              void* d_out, int out_size)
{
    const float* x    = (const float*)d_in[0];
    const float* wgt  = (const float*)d_in[1];
    const float* bias = (const float*)d_in[2];
    float* out        = (float*)d_out;

    cudaFuncSetAttribute(conv_mma_kernel,
                         cudaFuncAttributeMaxDynamicSharedMemorySize, SM_DYN);

    {
        dim3 g(NPIX / 32, CIN / 32, NB + 1);   // 98 x 8 x 33 (z=32: weights)
        dim3 b(32, 8);
        prepass_all<<<g, b>>>(x, wgt);
    }

    dim3 grid(HH / 2, KOUT / MTILE, NB);   // 28 x 2 x 32 = 1792 CTAs
    conv_mma_kernel<<<grid, 256, SM_DYN>>>(bias, out);
}

// round 11
// speedup vs baseline: 1.0337x; 1.0337x over previous
#include <cuda_runtime.h>
#include <cstdint>

#define NB    32
#define CIN   256
#define HH    56
#define WW    56
#define KOUT  256
#define NPIX  (HH*WW)        // 3136
#define KDIM  (CIN*9)        // 2304
#define NCHUNK 72            // 2304 / 32 k-chunks
#define NTILES 1792          // 28 r-tiles x 2 k-groups x 32 images

#define MTILE 128
#define NTILE 112

#define A_OFF  0
#define B_OFF  16384
#define STAGE  30720
#define SM_DYN (3*STAGE + 128)   // 92288/CTA -> 2 CTAs/SM

// ---------------- device scratch -------------------------------------------
__device__ __align__(16) float g_wt[KOUT * KDIM];
__device__ __align__(16) float g_xt[(size_t)NB * NPIX * CIN];
__device__ unsigned int g_tile_ctr;

// ---------------- PTX helpers ----------------------------------------------
__device__ __forceinline__ uint32_t smem_u32(const void* p) {
    uint32_t a;
    asm("{ .reg .u64 t; cvta.to.shared.u64 t, %1; cvt.u32.u64 %0, t; }"
        : "=r"(a) : "l"(p));
    return a;
}
__device__ __forceinline__ float to_tf32(float v) {
    uint32_t r;
    asm("cvt.rna.tf32.f32 %0, %1;" : "=r"(r) : "f"(v));
    return __uint_as_float(r);
}

#define CP16(dst, src, sz) \
    asm volatile("cp.async.cg.shared.global [%0], [%1], 16, %2;" \
                 :: "r"(dst), "l"(src), "r"(sz) : "memory")
#define CP_COMMIT() asm volatile("cp.async.commit_group;" ::: "memory")
#define CP_WAIT1()  asm volatile("cp.async.wait_group 1;" ::: "memory")

#define LDSM4(r, a) \
    asm volatile("ldmatrix.sync.aligned.m8n8.x4.shared.b16 {%0,%1,%2,%3}, [%4];" \
                 : "=r"((r)[0]),"=r"((r)[1]),"=r"((r)[2]),"=r"((r)[3]) : "r"(a))
#define LDSM2(r, a) \
    asm volatile("ldmatrix.sync.aligned.m8n8.x2.shared.b16 {%0,%1}, [%2];" \
                 : "=r"((r)[0]),"=r"((r)[1]) : "r"(a))

#define MMAT(d, a, b) \
    asm volatile("mma.sync.aligned.m16n8k8.row.col.f32.tf32.tf32.f32 " \
                 "{%0,%1,%2,%3}, {%4,%5,%6,%7}, {%8,%9}, {%0,%1,%2,%3};" \
                 : "+f"((d)[0]),"+f"((d)[1]),"+f"((d)[2]),"+f"((d)[3]) \
                 : "r"((a)[0]),"r"((a)[1]),"r"((a)[2]),"r"((a)[3]), \
                   "r"((b)[0]),"r"((b)[1]))

// ---------------- fused prepass ---------------------------------------------
__global__ void prepass_all(const float* __restrict__ x,
                            const float* __restrict__ w) {
    __shared__ float t[32][33];
    const int tx = threadIdx.x, ty = threadIdx.y;   // 32 x 8

    if (blockIdx.z < NB) {
        const int n  = blockIdx.z;
        const int p0 = blockIdx.x * 32;
        const int c0 = blockIdx.y * 32;

        const float* xb = x + ((size_t)n * CIN + c0) * NPIX + p0;
        #pragma unroll
        for (int yy = ty; yy < 32; yy += 8)
            t[yy][tx] = xb[(size_t)yy * NPIX + tx];
        __syncthreads();

        size_t ob = ((size_t)n * NPIX + p0) * CIN + c0;
        #pragma unroll
        for (int yy = ty; yy < 32; yy += 8)
            g_xt[ob + (size_t)yy * CIN + tx] = to_tf32(t[tx][yy]);
    } else {
        const int b = blockIdx.y * gridDim.x + blockIdx.x;   // 0..783
        const int tl = ty * 32 + tx;
        if (b == 0 && tl == 0) g_tile_ctr = 0u;   // reset work queue each launch
        for (int i = b * 256 + tl; i < KOUT * KDIM; i += 784 * 256) {
            int k = i / KDIM, r = i % KDIM;
            int c = r / 9, tap = r % 9;
            g_wt[k * KDIM + tap * CIN + c] = to_tf32(w[i]);
        }
    }
}

// ---------------- main kernel: persistent CTAs ------------------------------
__global__ __launch_bounds__(256, 2)
void conv_mma_kernel(const float* __restrict__ bias, float* __restrict__ out)
{
    extern __shared__ __align__(16) char dsm_raw[];
    __shared__ unsigned s_tile;

    const int tid = threadIdx.x;
    const int wid = tid >> 5;
    const int L   = tid & 31;
    const int wm  = wid & 3;
    const int wn  = wid >> 2;
    const int kso = (wid & 3) ^ ((wid >> 2) << 1);   // per-warp ks rotation

    uint32_t raw = smem_u32(dsm_raw);
    uint32_t sm  = (raw + 127u) & ~127u;
    uint32_t bufs[3] = { sm, sm + STAGE, sm + 2 * STAGE };

    // ---- per-lane ldmatrix constants ----
    const int arowL = ((L >> 3) & 1) * 8 + (L & 7);
    const int akg   = L >> 4;
    const int bprowL = wn * 56 + ((L >> 4) & 1) * 8 + (L & 7);
    const int bpkg   = (L >> 3) & 1;
    const int bsrowL = wn * 56 + 48 + (L & 7);
    const int bskg   = (L >> 3) & 1;

    // ---- staging coords + state ----
    int sr0 = 0, sk0 = 0, sn = 0;
    uint32_t giB[4], giA[4], szmask;

    auto decode = [&](int t) {
        sn = t / 56;
        const int rem = t - sn * 56;
        sk0 = (rem & 1) << 7;
        sr0 = (rem >> 1) << 1;
    };
    auto setup_tap = [&](int tap) {
        const int kh = tap / 3 - 1, kw = tap % 3 - 1;
        uint32_t m = 0;
        #pragma unroll
        for (int s = 0; s < 4; ++s) {
            const int i = tid + s * 256;
            const int p = i >> 3, v = i & 7;
            const int r = sr0 + p / 56 + kh;
            const int w = p % 56 + kw;
            const bool in = ((unsigned)r < HH) & ((unsigned)w < WW);
            giB[s] = in ? (uint32_t)((sn * NPIX + r * WW + w) * CIN + v * 4) : 0u;
            if (in) m |= (1u << s);
            giA[s] = (uint32_t)((sk0 + p) * KDIM + tap * CIN + v * 4);
        }
        szmask = m;
    };
    auto slot_off = [&](int s) -> uint32_t {
        const int i = tid + s * 256;
        const int p = i >> 3, v = i & 7;
        uint32_t bo = (uint32_t)(p << 7) + (v << 4);
        return bo ^ ((bo >> 3) & 0x70);
    };
    auto emit_all = [&](uint32_t sb) {
        #pragma unroll
        for (int ss = 0; ss < 4; ++ss) {
            const uint32_t sz = ((szmask >> ss) & 1u) * 16u;
            if (ss < 3 || tid < 128)
                CP16(sb + B_OFF + slot_off(ss), g_xt + giB[ss], sz);
            CP16(sb + A_OFF + slot_off(ss), g_wt + giA[ss], 16u);
        }
    };
    auto advance = [&]() {
        #pragma unroll
        for (int s = 0; s < 4; ++s) { giB[s] += 32; giA[s] += 32; }
    };

    float acc[2][7][4];
    #pragma unroll
    for (int mi = 0; mi < 2; ++mi)
        #pragma unroll
        for (int ni = 0; ni < 7; ++ni)
            #pragma unroll
            for (int q = 0; q < 4; ++q)
                acc[mi][ni][q] = 0.0f;

    // ---- acquire first tile, stage its chunks 0,1 ----
    if (tid == 0) s_tile = atomicAdd(&g_tile_ctr, 1u);
    __syncthreads();
    if ((int)s_tile >= NTILES) return;
    decode((int)s_tile);
    setup_tap(0);
    emit_all(bufs[0]); CP_COMMIT(); advance();
    emit_all(bufs[1]); CP_COMMIT(); advance();

    int r0 = sr0, k0 = sk0, n = sn;      // compute-tile coords
    bool vS = true;                      // staging-tile validity
    int rd = 0, wr = 2, lc = 0;

    // ---- persistent main loop (global chunk stream) ----
    while (true) {
        CP_WAIT1();
        __syncthreads();

        // fetch next tile id two chunks before the boundary
        if (lc == 69 && tid == 0) s_tile = atomicAdd(&g_tile_ctr, 1u);

        // staging-tile switch at lc==70 (s_tile published by this iter's barrier)
        if (lc == 70) {
            const int tn = (int)s_tile;
            vS = (tn < NTILES);
            if (vS) { decode(tn); setup_tap(0); }
        }

        // stage one chunk into the ring
        if (lc < 70) {
            const int ce = lc + 2;
            if ((ce & 7) == 0) setup_tap(ce >> 3);
            emit_all(bufs[wr]); CP_COMMIT(); advance();
        } else if (vS) {
            emit_all(bufs[wr]); CP_COMMIT(); advance();
        } else {
            CP_COMMIT();                 // keep group accounting aligned
        }

        // ---- compute chunk lc of the current tile ----
        {
            const uint32_t sb = bufs[rd];
            const uint32_t sA = sb + A_OFF, sB = sb + B_OFF;
            #pragma unroll
            for (int kk = 0; kk < 4; ++kk) {
                const int ks = (kk + kso) & 3;
                uint32_t bt[7][2];
                #pragma unroll
                for (int pi = 0; pi < 3; ++pi) {
                    const int row = bprowL + pi * 16;
                    const int c16 = (ks * 2 + bpkg) ^ (row & 7);
                    LDSM4(&bt[pi * 2][0], sB + (uint32_t)(row << 7) + (c16 << 4));
                }
                {
                    const int c16 = (ks * 2 + bskg) ^ (bsrowL & 7);
                    LDSM2(bt[6], sB + (uint32_t)(bsrowL << 7) + (c16 << 4));
                }
                uint32_t at[2][4];
                #pragma unroll
                for (int mi = 0; mi < 2; ++mi) {
                    const int row = wm * 32 + mi * 16 + arowL;
                    const int c16 = (ks * 2 + akg) ^ (row & 7);
                    LDSM4(at[mi], sA + (uint32_t)(row << 7) + (c16 << 4));
                }
                #pragma unroll
                for (int mi = 0; mi < 2; ++mi)
                    #pragma unroll
                    for (int ni = 0; ni < 7; ++ni)
                        MMAT(acc[mi][ni], at[mi], bt[ni]);
            }
        }

        rd = (rd == 2) ? 0 : rd + 1;
        wr = (wr == 2) ? 0 : wr + 1;

        if (lc == 71) {
            // ---- epilogue for the finished tile (hides next tile's refill) ----
            const int gID = L >> 2;
            const int tig = L & 3;
            const int r   = r0 + wn;
            #pragma unroll
            for (int mi = 0; mi < 2; ++mi) {
                const int kbase = k0 + wm * 32 + mi * 16 + gID;
                const float b0 = bias[kbase];
                const float b1 = bias[kbase + 8];
                float* o0 = out + (((size_t)n * KOUT + kbase)     * HH + r) * WW;
                float* o1 = out + (((size_t)n * KOUT + kbase + 8) * HH + r) * WW;
                #pragma unroll
                for (int ni = 0; ni < 7; ++ni) {
                    const int c = ni * 8 + tig * 2;
                    float2 v0 = make_float2(acc[mi][ni][0] + b0, acc[mi][ni][1] + b0);
                    float2 v1 = make_float2(acc[mi][ni][2] + b1, acc[mi][ni][3] + b1);
                    *reinterpret_cast<float2*>(o0 + c) = v0;
                    *reinterpret_cast<float2*>(o1 + c) = v1;
                }
            }
            if (!vS) break;              // no further tiles: done
            #pragma unroll
            for (int mi = 0; mi < 2; ++mi)
                #pragma unroll
                for (int ni = 0; ni < 7; ++ni)
                    #pragma unroll
                    for (int q = 0; q < 4; ++q)
                        acc[mi][ni][q] = 0.0f;
            r0 = sr0; k0 = sk0; n = sn;  // adopt staged tile as compute tile
            lc = 0;
        } else {
            ++lc;
        }
    }
}

// ---------------- launch -----------------------------------------------------
extern "C" void kernel_launch(void* const* d_in, const int* in_sizes, int n_in,
                              void* d_out, int out_size)
{
    const float* x    = (const float*)d_in[0];
    const float* wgt  = (const float*)d_in[1];
    const float* bias = (const float*)d_in[2];
    float* out        = (float*)d_out;

    cudaFuncSetAttribute(conv_mma_kernel,
                         cudaFuncAttributeMaxDynamicSharedMemorySize, SM_DYN);

    {
        dim3 g(NPIX / 32, CIN / 32, NB + 1);   // z=32 branch also resets work queue
        dim3 b(32, 8);
        prepass_all<<<g, b>>>(x, wgt);
    }

    conv_mma_kernel<<<296, 256, SM_DYN>>>(bias, out);   // persistent: 2 CTAs/SM
}